// round 12
// baseline (speedup 1.0000x reference)
#include <cuda_runtime.h>
#include <cstdint>

// HierarchicalSoftmax fused single kernel:
//   out[b, c*320 + t] = (in[b]·Wtop[:,c] + btop[c]) + (in[b]·Wbot[t] + bbot[t])
// One CTA per batch row (grid=1024, TB=640):
//   compute phase: threads 0-319 -> one bottom dot each (Wbot row, f4 loads)
//                  threads 320-639 -> one top column each (coalesced Wtop reads)
//   stream phase:  640 | row/4 and 80 | 640 => i%80 == tid%80 (constant!),
//                  class = tid/80 + 8k  -> minimal inner loop, f4 streaming stores.
// No scratch globals, no second kernel, no PDL: zero inter-kernel overhead.

#define BATCH      1024
#define NHID       128
#define NCLASSES   320
#define PER_CLASS  320
#define ROW_OUT    (NCLASSES * PER_CLASS)   // 102400
#define ROW_F4     (ROW_OUT / 4)            // 25600
#define TB         640
#define NITER      (ROW_F4 / TB)            // 40

__global__ __launch_bounds__(TB) void hs_fused(
    const float* __restrict__ in,     // [1024, 128]
    const float* __restrict__ Wtop,   // [128, 320] (k-major)
    const float* __restrict__ btop,   // [320]
    const float* __restrict__ Wbot,   // [320, 128] (row-major)
    const float* __restrict__ bbot,   // [320]
    float* __restrict__ out)          // [1024, 102400]
{
    __shared__ float in_s[NHID];
    __shared__ float top_s[NCLASSES];
    __shared__ float bot_s[PER_CLASS];

    const int b   = blockIdx.x;
    const int tid = threadIdx.x;

    // Load the input row (128 floats).
    if (tid < NHID / 4) {
        reinterpret_cast<float4*>(in_s)[tid] =
            reinterpret_cast<const float4*>(in + (size_t)b * NHID)[tid];
    }
    __syncthreads();

    // ---- Compute phase: 640 dots, one per thread ----
    if (tid < PER_CLASS) {
        // Bottom dot t = tid: Wbot row is contiguous -> 32 x LDG.128.
        const int t = tid;
        float s = bbot[t];
        const float4* w4 = reinterpret_cast<const float4*>(Wbot + (size_t)t * NHID);
        #pragma unroll 8
        for (int k = 0; k < NHID / 4; k++) {
            float4 w = w4[k];
            s = fmaf(in_s[4 * k + 0], w.x, s);
            s = fmaf(in_s[4 * k + 1], w.y, s);
            s = fmaf(in_s[4 * k + 2], w.z, s);
            s = fmaf(in_s[4 * k + 3], w.w, s);
        }
        bot_s[t] = s;
    } else {
        // Top column j = tid-320: lanes j consecutive -> coalesced 128B per k.
        const int j = tid - PER_CLASS;
        float s = btop[j];
        const float* w = Wtop + j;
        #pragma unroll 8
        for (int k = 0; k < NHID; k++)
            s = fmaf(in_s[k], w[k * NCLASSES], s);
        top_s[j] = s;
    }
    __syncthreads();

    // ---- Stream phase: 25600 f4 stores, 40 iters/thread ----
    // i = tid + 640k:  i%80 = tid%80 (constant)  ->  one bottom f4 register;
    //                  i/80 = tid/80 + 8k        ->  class via simple add.
    const float4 bv = reinterpret_cast<const float4*>(bot_s)[tid % 80];
    const int    c0 = tid / 80;                       // 0..7
    const float* tp = top_s + c0;

    float4* __restrict__ out4 =
        reinterpret_cast<float4*>(out + (size_t)b * ROW_OUT);

    #pragma unroll 8
    for (int k = 0; k < NITER; k++) {
        const float tv = tp[8 * k];                   // LDS broadcast (<=2 vals/warp)
        float4 v = bv;
        v.x += tv; v.y += tv; v.z += tv; v.w += tv;
        __stcs(out4 + k * TB + tid, v);               // streaming store
    }
}

extern "C" void kernel_launch(void* const* d_in, const int* in_sizes, int n_in,
                              void* d_out, int out_size) {
    const float* in   = (const float*)d_in[0];
    const float* Wtop = (const float*)d_in[1];
    const float* btop = (const float*)d_in[2];
    const float* Wbot = (const float*)d_in[3];
    const float* bbot = (const float*)d_in[4];
    float* out = (float*)d_out;

    hs_fused<<<BATCH, TB>>>(in, Wtop, btop, Wbot, bbot, out);
}

// round 13
// speedup vs baseline: 1.3323x; 1.3323x over previous
#include <cuda_runtime.h>
#include <cstdint>

// HierarchicalSoftmax: out[b, c*320 + t] = top[b,c] + bottom[b,t]
// Asymmetric split:
//   Kernel A: f32x2 GEMM computes ONLY bot = in @ Wbot^T + bbot (320 CTAs).
//   Kernel B: stream (grid=4096, TB=256, quarter-rows). Each CTA computes its
//             own 80 top logits in the PDL pre-sync window (overlaps GEMM),
//             then waits (HW gridsync) only for bot, then streams stores.

#define BATCH      1024
#define NHID       128
#define NCLASSES   320
#define PER_CLASS  320
#define ROW_OUT    (NCLASSES * PER_CLASS)   // 102400
#define TB         256
#define QSEGS      4
#define CLS_PER_Q  (NCLASSES / QSEGS)       // 80
#define F4_PER_Q   (CLS_PER_Q * PER_CLASS / 4)  // 6400

// GEMM tiling (bot only)
#define BM 64
#define BN 16
#define ASTR 66
#define BSTR 17

__device__ float g_bot[BATCH * PER_CLASS];

__device__ __forceinline__ uint32_t smem_u32(const void* p) {
    uint32_t a;
    asm("{ .reg .u64 t; cvta.to.shared.u64 t, %1; cvt.u32.u64 %0, t; }" : "=r"(a) : "l"(p));
    return a;
}
__device__ __forceinline__ unsigned long long lds64(uint32_t addr) {
    unsigned long long v;
    asm volatile("ld.shared.b64 %0, [%1];" : "=l"(v) : "r"(addr));
    return v;
}
__device__ __forceinline__ unsigned long long dup2(float x) {
    unsigned long long r;
    asm("mov.b64 %0, {%1, %1};" : "=l"(r) : "f"(x));
    return r;
}
__device__ __forceinline__ void ffma2(unsigned long long& d,
                                      unsigned long long a, unsigned long long b) {
    asm("fma.rn.f32x2 %0, %1, %2, %0;" : "+l"(d) : "l"(a), "l"(b));
}
__device__ __forceinline__ void unpk(float& lo, float& hi, unsigned long long v) {
    asm("mov.b64 {%0, %1}, %2;" : "=f"(lo), "=f"(hi) : "l"(v));
}

// ---------------- Kernel A: bot-only packed-f32x2 GEMM ----------------
__global__ __launch_bounds__(128) void hs_gemm_bot(
    const float* __restrict__ in,     // [1024, 128]
    const float* __restrict__ Wbot,   // [320, 128]
    const float* __restrict__ bbot)   // [320]
{
    // Early trigger: stream grid ramps + runs its top-compute while we execute.
    cudaTriggerProgrammaticLaunchCompletion();

    __shared__ float A2[NHID * ASTR];
    __shared__ float B2[NHID * BSTR];

    const int bm  = blockIdx.x;          // 0..15
    const int bn  = blockIdx.y;          // 0..19 -> bot cols bn*16..+16
    const int tid = threadIdx.x;
    const int jbase = bn * BN;

    {
        const float* src = in + (size_t)bm * BM * NHID + tid;
        #pragma unroll 8
        for (int row = 0; row < BM; row++)
            A2[tid * ASTR + row] = src[(size_t)row * NHID];
    }

    {   // B2[k][jj] = Wbot[(jbase+jj)*128 + k]
        const int klo = tid & 31;
        const int j0  = tid >> 5;
        #pragma unroll
        for (int it = 0; it < 4; it++) {
            const int jj = it * 4 + j0;
            const float* src = Wbot + (size_t)(jbase + jj) * NHID;
            #pragma unroll
            for (int kk = 0; kk < 4; kk++) {
                const int k = kk * 32 + klo;
                B2[k * BSTR + jj] = src[k];
            }
        }
    }
    __syncthreads();

    const int tr = tid >> 3;
    const int tc = tid & 7;

    unsigned long long acc00 = 0, acc01 = 0, acc10 = 0, acc11 = 0;
    const uint32_t sA = smem_u32(A2) + (tr * 4) * 4;
    const float* Bp = B2 + tc * 2;

    #pragma unroll 4
    for (int k = 0; k < NHID; k++) {
        unsigned long long a01 = lds64(sA + k * (ASTR * 4));
        unsigned long long a23 = lds64(sA + k * (ASTR * 4) + 8);
        unsigned long long b0 = dup2(Bp[k * BSTR + 0]);
        unsigned long long b1 = dup2(Bp[k * BSTR + 1]);
        ffma2(acc00, a01, b0); ffma2(acc01, a01, b1);
        ffma2(acc10, a23, b0); ffma2(acc11, a23, b1);
    }

    const int row0 = bm * BM + tr * 4;
    const int jg   = jbase + tc * 2;
    float r0c0, r1c0, r2c0, r3c0, r0c1, r1c1, r2c1, r3c1;
    unpk(r0c0, r1c0, acc00); unpk(r2c0, r3c0, acc10);
    unpk(r0c1, r1c1, acc01); unpk(r2c1, r3c1, acc11);

    const float bias0 = bbot[jg], bias1 = bbot[jg + 1];
    float2 v0 = {r0c0 + bias0, r0c1 + bias1};
    float2 v1 = {r1c0 + bias0, r1c1 + bias1};
    float2 v2 = {r2c0 + bias0, r2c1 + bias1};
    float2 v3 = {r3c0 + bias0, r3c1 + bias1};
    *reinterpret_cast<float2*>(g_bot + (size_t)(row0 + 0) * PER_CLASS + jg) = v0;
    *reinterpret_cast<float2*>(g_bot + (size_t)(row0 + 1) * PER_CLASS + jg) = v1;
    *reinterpret_cast<float2*>(g_bot + (size_t)(row0 + 2) * PER_CLASS + jg) = v2;
    *reinterpret_cast<float2*>(g_bot + (size_t)(row0 + 3) * PER_CLASS + jg) = v3;
}

// ---------------- Kernel B: stream + private top-compute ----------------
__global__ __launch_bounds__(TB) void hs_stream(
    const float* __restrict__ in,
    const float* __restrict__ Wtop,   // [128, 320] k-major
    const float* __restrict__ btop,
    float* __restrict__ out)
{
    __shared__ float  in_s[NHID];
    __shared__ float  top_s[CLS_PER_Q];
    __shared__ float4 bot_s[PER_CLASS / 4];

    const int b   = blockIdx.x >> 2;
    const int q   = blockIdx.x & 3;
    const int tid = threadIdx.x;

    // ---- Pre-sync window: everything independent of g_bot ----
    if (tid < NHID / 4) {
        reinterpret_cast<float4*>(in_s)[tid] =
            reinterpret_cast<const float4*>(in + (size_t)b * NHID)[tid];
    }

    int cm[5];
    #pragma unroll
    for (int m = 0; m < 5; m++) cm[m] = (tid + TB * m) / 80;   // 0..15

    float4* __restrict__ out4 =
        reinterpret_cast<float4*>(out + (size_t)b * ROW_OUT) + q * F4_PER_Q;

    __syncthreads();   // in_s ready

    // 80 private top logits: one dot per thread (tid<80), coalesced Wtop reads.
    if (tid < CLS_PER_Q) {
        const int c = q * CLS_PER_Q + tid;
        float s = btop[c];
        const float* w = Wtop + c;
        #pragma unroll 8
        for (int k = 0; k < NHID; k++)
            s = fmaf(in_s[k], w[k * NCLASSES], s);
        top_s[tid] = s;
    }

    // ---- HW wait for GEMM-bot completion ----
    cudaGridDependencySynchronize();

    if (tid < 80) {
        bot_s[tid] = reinterpret_cast<const float4*>(g_bot + b * PER_CLASS)[tid];
    }
    __syncthreads();   // top_s + bot_s visible to all

    float4 bv[5];
    #pragma unroll
    for (int m = 0; m < 5; m++)
        bv[m] = bot_s[(tid + TB * m) % 80];

    #pragma unroll
    for (int p = 0; p < 5; p++) {
        #pragma unroll
        for (int m = 0; m < 5; m++) {
            const float tv = top_s[cm[m] + 16 * p];
            float4 v = bv[m];
            v.x += tv; v.y += tv; v.z += tv; v.w += tv;
            __stcs(out4 + p * (5 * TB) + m * TB + tid, v);
        }
    }
}

extern "C" void kernel_launch(void* const* d_in, const int* in_sizes, int n_in,
                              void* d_out, int out_size) {
    const float* in   = (const float*)d_in[0];
    const float* Wtop = (const float*)d_in[1];
    const float* btop = (const float*)d_in[2];
    const float* Wbot = (const float*)d_in[3];
    const float* bbot = (const float*)d_in[4];
    float* out = (float*)d_out;

    // Bot-only GEMM: normal launch (serializes against previous replay).
    hs_gemm_bot<<<dim3(BATCH / BM, PER_CLASS / BN), 128>>>(in, Wbot, bbot);

    // Stream with PDL: top-compute runs in the pre-sync window.
    cudaLaunchConfig_t cfg = {};
    cfg.gridDim  = dim3(BATCH * QSEGS, 1, 1);             // 4096
    cfg.blockDim = dim3(TB, 1, 1);
    cfg.dynamicSmemBytes = 0;
    cfg.stream = 0;
    cudaLaunchAttribute attr[1];
    attr[0].id = cudaLaunchAttributeProgrammaticStreamSerialization;
    attr[0].val.programmaticStreamSerializationAllowed = 1;
    cfg.attrs = attr;
    cfg.numAttrs = 1;
    cudaLaunchKernelEx(&cfg, hs_stream, in, Wtop, btop, out);
}

// round 14
// speedup vs baseline: 1.4150x; 1.0621x over previous
#include <cuda_runtime.h>
#include <cstdint>

// HierarchicalSoftmax: out[b, c*320 + t] = top[b,c] + bottom[b,t]
// Phase A: f32x2 GEMM, 8x4 microtile (64 thr, BM=64 BN=32, 320 CTAs) —
//          0.875 instr/FMA vs 1.25 before.
// Phase B: R4's best-measured stream loop (TB=128, grid=8192, 73.5% DRAM),
//          PDL-launched with pre-sync setup.

#define BATCH      1024
#define NHID       128
#define NCLASSES   320
#define PER_CLASS  320
#define ROW_OUT    (NCLASSES * PER_CLASS)   // 102400
#define SEGS       8
#define CLS_PER_SEG (NCLASSES / SEGS)       // 40
#define F4_PER_SEG (CLS_PER_SEG * PER_CLASS / 4)  // 3200
#define TB         128

// GEMM tiling: BM=64, BN=32, 64 threads, microtile 8 rows x 4 cols
#define BM 64
#define BN 32
#define GT 64
#define ASTR 66    // A2[k][row], 264B rows
#define BSTR 33    // B2[k][jj],  132B rows

__device__ float g_top[BATCH * NCLASSES];
__device__ float g_bot[BATCH * PER_CLASS];

__device__ __forceinline__ uint32_t smem_u32(const void* p) {
    uint32_t a;
    asm("{ .reg .u64 t; cvta.to.shared.u64 t, %1; cvt.u32.u64 %0, t; }" : "=r"(a) : "l"(p));
    return a;
}
__device__ __forceinline__ unsigned long long lds64(uint32_t addr) {
    unsigned long long v;
    asm volatile("ld.shared.b64 %0, [%1];" : "=l"(v) : "r"(addr));
    return v;
}
__device__ __forceinline__ unsigned long long dup2(float x) {
    unsigned long long r;
    asm("mov.b64 %0, {%1, %1};" : "=l"(r) : "f"(x));
    return r;
}
__device__ __forceinline__ void ffma2(unsigned long long& d,
                                      unsigned long long a, unsigned long long b) {
    asm("fma.rn.f32x2 %0, %1, %2, %0;" : "+l"(d) : "l"(a), "l"(b));
}
__device__ __forceinline__ void unpk(float& lo, float& hi, unsigned long long v) {
    asm("mov.b64 {%0, %1}, %2;" : "=f"(lo), "=f"(hi) : "l"(v));
}

// ---------------- Kernel A: 8x4-microtile packed-f32x2 dual GEMM ----------------
__global__ __launch_bounds__(GT) void hs_gemm(
    const float* __restrict__ in,     // [1024, 128]
    const float* __restrict__ Wtop,   // [128, 320] k-major
    const float* __restrict__ btop,   // [320]
    const float* __restrict__ Wbot,   // [320, 128] row-major
    const float* __restrict__ bbot)   // [320]
{
    cudaTriggerProgrammaticLaunchCompletion();

    __shared__ float A2[NHID * ASTR];   // [k][row] 33.8 KB
    __shared__ float B2[NHID * BSTR];   // [k][jj]  16.9 KB

    const int bm  = blockIdx.x;                 // 0..15
    const int bn  = blockIdx.y;                 // 0..19
    const int tid = threadIdx.x;
    const bool is_top = (bn < NCLASSES / BN);   // bn < 10
    const int  jbase  = bn * BN;

    // A tile: 64 rows x 128 k. f4 global loads, scatter STS into [k][row].
    {
        const float4* srcA = reinterpret_cast<const float4*>(in + (size_t)bm * BM * NHID);
        #pragma unroll
        for (int it = 0; it < 32; it++) {
            const int idx = it * GT + tid;     // 0..2047
            const int row = idx >> 5;          // 0..63
            const int k4  = idx & 31;          // f4 index in k
            float4 v = srcA[idx];
            float* d = A2 + (k4 * 4) * ASTR + row;
            d[0] = v.x; d[ASTR] = v.y; d[2 * ASTR] = v.z; d[3 * ASTR] = v.w;
        }
    }

    // B tile: 32 cols x 128 k into [k][jj].
    if (is_top) {
        const int jj = tid & 31;
        const int k0 = tid >> 5;               // 0..1
        #pragma unroll
        for (int it = 0; it < 64; it++) {
            const int k = it * 2 + k0;
            B2[k * BSTR + jj] = Wtop[k * NCLASSES + jbase + jj];
        }
    } else {
        const int klo = tid & 31;
        const int j0  = tid >> 5;              // 0..1
        #pragma unroll
        for (int it = 0; it < 16; it++) {
            const int jj = it * 2 + j0;        // 0..31
            const float4* srcB = reinterpret_cast<const float4*>(
                Wbot + (size_t)(jbase - NCLASSES + jj) * NHID);
            float4 v = srcB[klo];
            float* d = B2 + (klo * 4) * BSTR + jj;
            d[0] = v.x; d[BSTR] = v.y; d[2 * BSTR] = v.z; d[3 * BSTR] = v.w;
        }
    }
    __syncthreads();

    // Microtile: tr 0..7 -> rows tr*8..+8 (4 f32x2 pairs), tc 0..7 -> cols tc*4..+4.
    const int tr = tid >> 3;
    const int tc = tid & 7;

    unsigned long long acc[4][4];   // [row-pair p][col c]
    #pragma unroll
    for (int p = 0; p < 4; p++)
        #pragma unroll
        for (int c = 0; c < 4; c++) acc[p][c] = 0;

    const uint32_t sA = smem_u32(A2) + tr * 32;    // +k*264 per step
    const float* Bp = B2 + tc * 4;                 // +k*33 per step

    #pragma unroll 4
    for (int k = 0; k < NHID; k++) {
        const uint32_t a = sA + k * (ASTR * 4);
        unsigned long long a0 = lds64(a);
        unsigned long long a1 = lds64(a + 8);
        unsigned long long a2 = lds64(a + 16);
        unsigned long long a3 = lds64(a + 24);
        const float* bk = Bp + k * BSTR;
        unsigned long long b0 = dup2(bk[0]);
        unsigned long long b1 = dup2(bk[1]);
        unsigned long long b2 = dup2(bk[2]);
        unsigned long long b3 = dup2(bk[3]);
        ffma2(acc[0][0], a0, b0); ffma2(acc[0][1], a0, b1);
        ffma2(acc[0][2], a0, b2); ffma2(acc[0][3], a0, b3);
        ffma2(acc[1][0], a1, b0); ffma2(acc[1][1], a1, b1);
        ffma2(acc[1][2], a1, b2); ffma2(acc[1][3], a1, b3);
        ffma2(acc[2][0], a2, b0); ffma2(acc[2][1], a2, b1);
        ffma2(acc[2][2], a2, b2); ffma2(acc[2][3], a2, b3);
        ffma2(acc[3][0], a3, b0); ffma2(acc[3][1], a3, b1);
        ffma2(acc[3][2], a3, b2); ffma2(acc[3][3], a3, b3);
    }

    // Epilogue: bias + 8 rows x float4.
    const int row0 = bm * BM + tr * 8;
    float bias[4];
    float* dst;
    int joff;
    if (is_top) {
        dst = g_top; joff = jbase + tc * 4;
        #pragma unroll
        for (int c = 0; c < 4; c++) bias[c] = btop[joff + c];
    } else {
        dst = g_bot; joff = jbase - NCLASSES + tc * 4;
        #pragma unroll
        for (int c = 0; c < 4; c++) bias[c] = bbot[joff + c];
    }

    #pragma unroll
    for (int p = 0; p < 4; p++) {
        float lo[4], hi[4];
        #pragma unroll
        for (int c = 0; c < 4; c++) unpk(lo[c], hi[c], acc[p][c]);
        float4 vlo = {lo[0] + bias[0], lo[1] + bias[1], lo[2] + bias[2], lo[3] + bias[3]};
        float4 vhi = {hi[0] + bias[0], hi[1] + bias[1], hi[2] + bias[2], hi[3] + bias[3]};
        *reinterpret_cast<float4*>(dst + (size_t)(row0 + 2 * p)     * 320 + joff) = vlo;
        *reinterpret_cast<float4*>(dst + (size_t)(row0 + 2 * p + 1) * 320 + joff) = vhi;
    }
}

// ---------------- Kernel B: R4's stream loop (TB=128, grid=8192) + PDL ----------------
__global__ __launch_bounds__(TB) void hs_stream(float* __restrict__ out)
{
    __shared__ float  top_s[CLS_PER_SEG];
    __shared__ float4 bot_s[PER_CLASS / 4];

    const int b   = blockIdx.x >> 3;
    const int seg = blockIdx.x & 7;
    const int tid = threadIdx.x;

    // Row-invariant setup before the dependency wait.
    int cm[5];
    #pragma unroll
    for (int m = 0; m < 5; m++) cm[m] = (tid + TB * m) / 80;

    float4* __restrict__ out4 =
        reinterpret_cast<float4*>(out + (size_t)b * ROW_OUT) + seg * F4_PER_SEG;

    cudaGridDependencySynchronize();

    if (tid < 80) {
        bot_s[tid] = reinterpret_cast<const float4*>(g_bot + b * PER_CLASS)[tid];
    } else if (tid < 80 + CLS_PER_SEG) {
        top_s[tid - 80] = g_top[b * NCLASSES + seg * CLS_PER_SEG + (tid - 80)];
    }
    __syncthreads();

    float4 bv[5];
    #pragma unroll
    for (int m = 0; m < 5; m++)
        bv[m] = bot_s[(tid + TB * m) % 80];

    #pragma unroll
    for (int p = 0; p < 5; p++) {
        #pragma unroll
        for (int m = 0; m < 5; m++) {
            const float tv = top_s[cm[m] + 8 * p];
            float4 v = bv[m];
            v.x += tv; v.y += tv; v.z += tv; v.w += tv;
            __stcs(out4 + p * (5 * TB) + m * TB + tid, v);
        }
    }
}

extern "C" void kernel_launch(void* const* d_in, const int* in_sizes, int n_in,
                              void* d_out, int out_size) {
    const float* in   = (const float*)d_in[0];
    const float* Wtop = (const float*)d_in[1];
    const float* btop = (const float*)d_in[2];
    const float* Wbot = (const float*)d_in[3];
    const float* bbot = (const float*)d_in[4];
    float* out = (float*)d_out;

    // GEMM: 16 x 20 = 320 CTAs, 64 threads. Normal launch (replay-safe).
    hs_gemm<<<dim3(BATCH / BM, (NCLASSES + PER_CLASS) / BN), GT>>>(
        in, Wtop, btop, Wbot, bbot);

    // Stream: PDL launch, R4 shape.
    cudaLaunchConfig_t cfg = {};
    cfg.gridDim  = dim3(BATCH * SEGS, 1, 1);    // 8192
    cfg.blockDim = dim3(TB, 1, 1);
    cfg.dynamicSmemBytes = 0;
    cfg.stream = 0;
    cudaLaunchAttribute attr[1];
    attr[0].id = cudaLaunchAttributeProgrammaticStreamSerialization;
    attr[0].val.programmaticStreamSerializationAllowed = 1;
    cfg.attrs = attr;
    cfg.numAttrs = 1;
    cudaLaunchKernelEx(&cfg, hs_stream, out);
}

// round 17
// speedup vs baseline: 1.4261x; 1.0078x over previous
#include <cuda_runtime.h>
#include <cstdint>

// HierarchicalSoftmax: out[b, c*320 + t] = top[b,c] + bottom[b,t]
// Phase A: f32x2 GEMM with BM=32 (1280 CTAs, 2x2 microtile) — latency-bound
//          kernel, so maximize cross-CTA overlap with small tiles.
// Phase B: R11's measured-best stream (TB=256, grid=4096, f4 __stcs), PDL.

#define BATCH      1024
#define NHID       128
#define NCLASSES   320
#define PER_CLASS  320
#define ROW_OUT    (NCLASSES * PER_CLASS)   // 102400
#define TB         256
#define QSEGS      4
#define CLS_PER_Q  (NCLASSES / QSEGS)       // 80
#define F4_PER_Q   (CLS_PER_Q * PER_CLASS / 4)  // 6400

// GEMM tiling: BM=32, BN=16, 128 threads, microtile 2x2 (one f32x2 row pair)
#define BM 32
#define BN 16
#define ASTR 34    // A2[k][row] stride (136B rows; lds64 8B-aligned)
#define BSTR 17    // B2[k][jj] stride

__device__ float g_top[BATCH * NCLASSES];
__device__ float g_bot[BATCH * PER_CLASS];

__device__ __forceinline__ uint32_t smem_u32(const void* p) {
    uint32_t a;
    asm("{ .reg .u64 t; cvta.to.shared.u64 t, %1; cvt.u32.u64 %0, t; }" : "=r"(a) : "l"(p));
    return a;
}
__device__ __forceinline__ unsigned long long lds64(uint32_t addr) {
    unsigned long long v;
    asm volatile("ld.shared.b64 %0, [%1];" : "=l"(v) : "r"(addr));
    return v;
}
__device__ __forceinline__ unsigned long long dup2(float x) {
    unsigned long long r;
    asm("mov.b64 %0, {%1, %1};" : "=l"(r) : "f"(x));
    return r;
}
__device__ __forceinline__ void ffma2(unsigned long long& d,
                                      unsigned long long a, unsigned long long b) {
    asm("fma.rn.f32x2 %0, %1, %2, %0;" : "+l"(d) : "l"(a), "l"(b));
}
__device__ __forceinline__ void unpk(float& lo, float& hi, unsigned long long v) {
    asm("mov.b64 {%0, %1}, %2;" : "=f"(lo), "=f"(hi) : "l"(v));
}

// ---------------- Kernel A: BM=32 packed-f32x2 dual GEMM ----------------
__global__ __launch_bounds__(128) void hs_gemm(
    const float* __restrict__ in,     // [1024, 128]
    const float* __restrict__ Wtop,   // [128, 320] k-major
    const float* __restrict__ btop,   // [320]
    const float* __restrict__ Wbot,   // [320, 128] row-major
    const float* __restrict__ bbot)   // [320]
{
    cudaTriggerProgrammaticLaunchCompletion();

    __shared__ float A2[NHID * ASTR];   // [k][row] 17.4 KB
    __shared__ float B2[NHID * BSTR];   // [k][jj]   8.7 KB

    const int bm  = blockIdx.x;                 // 0..31
    const int bn  = blockIdx.y;                 // 0..39
    const int tid = threadIdx.x;
    const bool is_top = (bn < NCLASSES / BN);   // bn < 20
    const int  jbase  = bn * BN;

    // A tile: per iter all 128 lanes (k=tid) read one input row coalesced.
    {
        const float* src = in + (size_t)bm * BM * NHID + tid;
        #pragma unroll 8
        for (int row = 0; row < BM; row++)
            A2[tid * ASTR + row] = src[(size_t)row * NHID];
    }

    // B tile: B2[k][jj] = weight(col jbase+jj, k)
    if (is_top) {
        const int jj = tid & 15;
        const int k0 = tid >> 4;               // 0..7
        #pragma unroll
        for (int it = 0; it < 16; it++) {
            const int k = it * 8 + k0;
            B2[k * BSTR + jj] = Wtop[k * NCLASSES + jbase + jj];
        }
    } else {
        const int klo = tid & 31;
        const int j0  = tid >> 5;              // 0..3
        #pragma unroll
        for (int it = 0; it < 4; it++) {
            const int jj = it * 4 + j0;
            const float* src = Wbot + (size_t)(jbase - NCLASSES + jj) * NHID;
            #pragma unroll
            for (int kk = 0; kk < 4; kk++) {
                const int k = kk * 32 + klo;
                B2[k * BSTR + jj] = src[k];
            }
        }
    }
    __syncthreads();

    // Microtile: tr 0..15 -> row pair {2tr, 2tr+1}; tc 0..7 -> cols tc*2..+2.
    const int tr = tid >> 3;
    const int tc = tid & 7;

    unsigned long long acc0 = 0, acc1 = 0;     // packed {row 2tr, 2tr+1} x col
    const uint32_t sA = smem_u32(A2) + tr * 8; // +k*136 per step
    const float* Bp = B2 + tc * 2;             // +k*17 per step

    #pragma unroll 8
    for (int k = 0; k < NHID; k++) {
        unsigned long long a01 = lds64(sA + k * (ASTR * 4));
        unsigned long long b0 = dup2(Bp[k * BSTR + 0]);
        unsigned long long b1 = dup2(Bp[k * BSTR + 1]);
        ffma2(acc0, a01, b0);
        ffma2(acc1, a01, b1);
    }

    const int row0 = bm * BM + tr * 2;
    const int jg   = jbase + tc * 2;
    float r0c0, r1c0, r0c1, r1c1;
    unpk(r0c0, r1c0, acc0);
    unpk(r0c1, r1c1, acc1);

    float bias0, bias1;
    float* dst;
    int stride, joff;
    if (is_top) {
        bias0 = btop[jg]; bias1 = btop[jg + 1];
        dst = g_top; stride = NCLASSES; joff = jg;
    } else {
        bias0 = bbot[jg - NCLASSES]; bias1 = bbot[jg - NCLASSES + 1];
        dst = g_bot; stride = PER_CLASS; joff = jg - NCLASSES;
    }
    float2 v0 = {r0c0 + bias0, r0c1 + bias1};
    float2 v1 = {r1c0 + bias0, r1c1 + bias1};
    *reinterpret_cast<float2*>(dst + (size_t)(row0 + 0) * stride + joff) = v0;
    *reinterpret_cast<float2*>(dst + (size_t)(row0 + 1) * stride + joff) = v1;
}

// ---------------- Kernel B: broadcast-add stream (R11-proven) ----------------
__global__ __launch_bounds__(TB) void hs_stream(float* __restrict__ out)
{
    __shared__ float  top_s[CLS_PER_Q];
    __shared__ float4 bot_s[PER_CLASS / 4];

    const int b   = blockIdx.x >> 2;
    const int q   = blockIdx.x & 3;
    const int tid = threadIdx.x;

    // Row-invariant setup before the dependency wait (overlaps GEMM).
    int cm[5];
    #pragma unroll
    for (int m = 0; m < 5; m++) cm[m] = (tid + TB * m) / 80;   // 0..15

    float4* __restrict__ out4 =
        reinterpret_cast<float4*>(out + (size_t)b * ROW_OUT) + q * F4_PER_Q;

    cudaGridDependencySynchronize();

    if (tid < 80) {
        bot_s[tid] = reinterpret_cast<const float4*>(g_bot + b * PER_CLASS)[tid];
    } else if (tid < 80 + CLS_PER_Q) {
        top_s[tid - 80] = g_top[b * NCLASSES + q * CLS_PER_Q + (tid - 80)];
    }
    __syncthreads();

    float4 bv[5];
    #pragma unroll
    for (int m = 0; m < 5; m++)
        bv[m] = bot_s[(tid + TB * m) % 80];

    #pragma unroll
    for (int p = 0; p < 5; p++) {
        #pragma unroll
        for (int m = 0; m < 5; m++) {
            const float tv = top_s[cm[m] + 16 * p];
            float4 v = bv[m];
            v.x += tv; v.y += tv; v.z += tv; v.w += tv;
            __stcs(out4 + p * (5 * TB) + m * TB + tid, v);
        }
    }
}

extern "C" void kernel_launch(void* const* d_in, const int* in_sizes, int n_in,
                              void* d_out, int out_size) {
    const float* in   = (const float*)d_in[0];
    const float* Wtop = (const float*)d_in[1];
    const float* btop = (const float*)d_in[2];
    const float* Wbot = (const float*)d_in[3];
    const float* bbot = (const float*)d_in[4];
    float* out = (float*)d_out;

    dim3 grid(BATCH / BM, (NCLASSES + PER_CLASS) / BN);   // 32 x 40 = 1280
    hs_gemm<<<grid, 128>>>(in, Wtop, btop, Wbot, bbot);

    cudaLaunchConfig_t cfg = {};
    cfg.gridDim  = dim3(BATCH * QSEGS, 1, 1);             // 4096
    cfg.blockDim = dim3(TB, 1, 1);
    cfg.dynamicSmemBytes = 0;
    cfg.stream = 0;
    cudaLaunchAttribute attr[1];
    attr[0].id = cudaLaunchAttributeProgrammaticStreamSerialization;
    attr[0].val.programmaticStreamSerializationAllowed = 1;
    cfg.attrs = attr;
    cfg.numAttrs = 1;
    cudaLaunchKernelEx(&cfg, hs_stream, out);
}